// round 10
// baseline (speedup 1.0000x reference)
#include <cuda_runtime.h>
#include <cuda_bf16.h>
#include <cstdint>
#include <math.h>

#define BB 2
#define SS 4096
#define DD 1024
#define HH 16
#define BLKSZ 64
#define NB 64          // S / BLK
#define NGB 2          // G / BLK
#define HDIM 64        // D / H
#define MROWS (BB*SS)  // 8192

// ---------------------------------------------------------------------------
// Device scratch (no allocation allowed)
// ---------------------------------------------------------------------------
__device__ __nv_bfloat16 g_x_hi[(size_t)MROWS*DD];
__device__ __nv_bfloat16 g_x_lo[(size_t)MROWS*DD];
__device__ __nv_bfloat16 g_c_hi[(size_t)MROWS*DD];
__device__ __nv_bfloat16 g_c_lo[(size_t)MROWS*DD];
__device__ __nv_bfloat16 g_w_hi[(size_t)4*DD*DD];   // [w][k][n] (native layout)
__device__ __nv_bfloat16 g_w_lo[(size_t)4*DD*DD];
// Q/K/V head-split bf16 hi/lo: [b,h,s,64]
__device__ __nv_bfloat16 g_qh[(size_t)BB*HH*SS*HDIM];
__device__ __nv_bfloat16 g_ql[(size_t)BB*HH*SS*HDIM];
__device__ __nv_bfloat16 g_kh[(size_t)BB*HH*SS*HDIM];
__device__ __nv_bfloat16 g_kl[(size_t)BB*HH*SS*HDIM];
__device__ __nv_bfloat16 g_vh[(size_t)BB*HH*SS*HDIM];
__device__ __nv_bfloat16 g_vl[(size_t)BB*HH*SS*HDIM];
// split-KV partials for heavy q-blocks
__device__ float g_po[(size_t)512*4096];
__device__ float g_pm[512*64];
__device__ float g_pl[512*64];

// ---------------------------------------------------------------------------
// mma.sync / ldmatrix / cp.async helpers (generic sm_80+ PTX)
// ---------------------------------------------------------------------------
__device__ __forceinline__ uint32_t smem_u32(const void* p) {
    uint32_t a;
    asm("{ .reg .u64 t; cvta.to.shared.u64 t, %1; cvt.u32.u64 %0, t; }" : "=r"(a) : "l"(p));
    return a;
}
__device__ __forceinline__ void ldsm_x4(uint32_t* r, uint32_t addr) {
    asm volatile("ldmatrix.sync.aligned.m8n8.x4.shared.b16 {%0,%1,%2,%3}, [%4];"
        : "=r"(r[0]), "=r"(r[1]), "=r"(r[2]), "=r"(r[3]) : "r"(addr));
}
__device__ __forceinline__ void ldsm_x2_trans(uint32_t* r, uint32_t addr) {
    asm volatile("ldmatrix.sync.aligned.m8n8.x2.trans.shared.b16 {%0,%1}, [%2];"
        : "=r"(r[0]), "=r"(r[1]) : "r"(addr));
}
__device__ __forceinline__ void mma_bf16(float (&c)[4], const uint32_t* a,
                                         uint32_t b0, uint32_t b1) {
    asm volatile("mma.sync.aligned.m16n8k16.row.col.f32.bf16.bf16.f32 "
        "{%0,%1,%2,%3}, {%4,%5,%6,%7}, {%8,%9}, {%0,%1,%2,%3};"
        : "+f"(c[0]), "+f"(c[1]), "+f"(c[2]), "+f"(c[3])
        : "r"(a[0]), "r"(a[1]), "r"(a[2]), "r"(a[3]), "r"(b0), "r"(b1));
}
__device__ __forceinline__ void cp_async16(uint32_t saddr, const void* gptr) {
    asm volatile("cp.async.cg.shared.global [%0], [%1], 16;" :: "r"(saddr), "l"(gptr));
}
#define CP_COMMIT asm volatile("cp.async.commit_group;")
#define CP_WAIT2  asm volatile("cp.async.wait_group 2;")
#define CP_WAIT1  asm volatile("cp.async.wait_group 1;")
#define CP_WAIT0  asm volatile("cp.async.wait_group 0;")

// pack two floats -> bf16x2 hi, bf16x2 lo (residual)
__device__ __forceinline__ uint32_t pack_hilo(float a, float b, uint32_t& lo_out) {
    __nv_bfloat162 h; h.x = __float2bfloat16(a); h.y = __float2bfloat16(b);
    __nv_bfloat162 l;
    l.x = __float2bfloat16(a - __bfloat162float(h.x));
    l.y = __float2bfloat16(b - __bfloat162float(h.y));
    lo_out = *(uint32_t*)&l;
    return *(uint32_t*)&h;
}

// ---------------------------------------------------------------------------
// Split tokens into bf16 hi/lo
// ---------------------------------------------------------------------------
__global__ __launch_bounds__(256) void split_x_kernel(const float* __restrict__ X)
{
    size_t i = (size_t)blockIdx.x * 256 + threadIdx.x;
    float4 v = ((const float4*)X)[i];
    float vs[4] = {v.x, v.y, v.z, v.w};
#pragma unroll
    for (int j = 0; j < 4; j++) {
        __nv_bfloat16 hi = __float2bfloat16(vs[j]);
        float lo = vs[j] - __bfloat162float(hi);
        g_x_hi[i * 4 + j] = hi;
        g_x_lo[i * 4 + j] = __float2bfloat16(lo);
    }
}

// ---------------------------------------------------------------------------
// Elementwise weight split
// ---------------------------------------------------------------------------
__global__ __launch_bounds__(256) void wsplit_kernel(
    const float* __restrict__ Wq, const float* __restrict__ Wk,
    const float* __restrict__ Wv, const float* __restrict__ Wu)
{
    const int w = blockIdx.y;
    const float* W = (w == 0) ? Wq : (w == 1) ? Wk : (w == 2) ? Wv : Wu;
    size_t i = (size_t)blockIdx.x * 256 + threadIdx.x;
    float4 v = ((const float4*)W)[i];
    float vs[4] = {v.x, v.y, v.z, v.w};
    size_t base = (size_t)w * DD * DD + i * 4;
#pragma unroll
    for (int j = 0; j < 4; j++) {
        __nv_bfloat16 hi = __float2bfloat16(vs[j]);
        float lo = vs[j] - __bfloat162float(hi);
        g_w_hi[base + j] = hi;
        g_w_lo[base + j] = __float2bfloat16(lo);
    }
}

// ---------------------------------------------------------------------------
// FUSED QKV GEMM: CTA = (head h, m-tile 128). N-tile = 3 weights x 64 cols.
// A-fragments loaded once per kk, reused for q/k/v -> 3x less A traffic.
// 3-stage cp.async pipeline, K-chunk 32. 8 warps: wm=wid&3 (32 M rows),
// wn=wid>>2 (32 N cols of each weight's 64-col head slice).
// ---------------------------------------------------------------------------
#define FSA 40            // A stride (b16)
#define FSB 72            // B stride (b16) per weight tile
#define F_AHI 0
#define F_ALO 10240       // 128*40*2
#define F_BW(w) (20480 + (w)*9216)    // hi; lo at +4608
#define FSTAGE 48128
#define FNSTAGE 3
#define FQKV_SMEM_BYTES (FNSTAGE*FSTAGE)   // 144384

__global__ __launch_bounds__(256) void qkv_fused_kernel()
{
    extern __shared__ __align__(16) char fsm[];
    const uint32_t smem_base = smem_u32(fsm);

    const int t    = threadIdx.x;
    const int lane = t & 31;
    const int wid  = t >> 5;
    const int wm   = wid & 3;
    const int wn   = wid >> 2;

    const int h  = blockIdx.x;           // head
    const int m0 = blockIdx.y * 128;
    const int nh = h * 64;               // column base within each weight

    float acc[3][2][4][4];
#pragma unroll
    for (int w = 0; w < 3; w++)
#pragma unroll
        for (int mi = 0; mi < 2; mi++)
#pragma unroll
            for (int nj = 0; nj < 4; nj++)
#pragma unroll
                for (int e = 0; e < 4; e++) acc[w][mi][nj][e] = 0.f;

    const int lrow = lane & 15;
    const int lcol = (lane >> 4) * 8;

    const int arow0 = t >> 2,          aseg0 = (t & 3) * 8;
    const int arow1 = (t + 256) >> 2,  aseg1 = ((t + 256) & 3) * 8;
    const int brow  = t >> 3,          bseg  = (t & 7) * 8;   // 32 rows x 64 cols

#define FQKV_PREFETCH(KC, SBUF) do {                                        \
    const int k0_ = (KC) * 32;                                              \
    const uint32_t sb_ = smem_base + (uint32_t)(SBUF) * FSTAGE;             \
    {   size_t go = (size_t)(m0 + arow0) * DD + k0_ + aseg0;                \
        uint32_t so = sb_ + (uint32_t)(arow0 * FSA + aseg0) * 2;            \
        cp_async16(so + F_AHI, g_x_hi + go);                                \
        cp_async16(so + F_ALO, g_x_lo + go); }                              \
    {   size_t go = (size_t)(m0 + arow1) * DD + k0_ + aseg1;                \
        uint32_t so = sb_ + (uint32_t)(arow1 * FSA + aseg1) * 2;            \
        cp_async16(so + F_AHI, g_x_hi + go);                                \
        cp_async16(so + F_ALO, g_x_lo + go); }                              \
    _Pragma("unroll")                                                       \
    for (int w_ = 0; w_ < 3; w_++) {                                        \
        size_t go = (size_t)w_ * DD * DD + (size_t)(k0_ + brow) * DD + nh + bseg; \
        uint32_t so = sb_ + F_BW(w_) + (uint32_t)(brow * FSB + bseg) * 2;   \
        cp_async16(so,        g_w_hi + go);                                 \
        cp_async16(so + 4608, g_w_lo + go);                                 \
    }                                                                       \
    CP_COMMIT; } while (0)

    FQKV_PREFETCH(0, 0);
    FQKV_PREFETCH(1, 1);

    int cs = 0;
    int ps = 2;
    for (int kc = 0; kc < 32; kc++) {
        if (kc <= 29) { CP_WAIT1; } else { CP_WAIT0; }
        __syncthreads();
        if (kc + 2 < 32) {
            FQKV_PREFETCH(kc + 2, ps);
            ps = (ps + 1 == FNSTAGE) ? 0 : ps + 1;
        }

        const uint32_t sb = smem_base + (uint32_t)cs * FSTAGE;
        cs = (cs + 1 == FNSTAGE) ? 0 : cs + 1;
#pragma unroll
        for (int kk = 0; kk < 2; kk++) {
            // A fragments: load once, reuse across 3 weights
            uint32_t ah[2][4], al[2][4];
#pragma unroll
            for (int mi = 0; mi < 2; mi++) {
                uint32_t off = (uint32_t)((wm * 32 + mi * 16 + lrow) * FSA + kk * 16 + lcol) * 2;
                ldsm_x4(ah[mi], sb + F_AHI + off);
                ldsm_x4(al[mi], sb + F_ALO + off);
            }
#pragma unroll
            for (int w = 0; w < 3; w++) {
                const uint32_t bw = sb + F_BW(w);
#pragma unroll
                for (int nj = 0; nj < 4; nj++) {
                    uint32_t off = (uint32_t)((kk * 16 + lrow) * FSB + wn * 32 + nj * 8) * 2;
                    uint32_t bh[2], bl[2];
                    ldsm_x2_trans(bh, bw + off);
                    ldsm_x2_trans(bl, bw + 4608 + off);
#pragma unroll
                    for (int mi = 0; mi < 2; mi++) {
                        mma_bf16(acc[w][mi][nj], ah[mi], bh[0], bh[1]);
                        mma_bf16(acc[w][mi][nj], ah[mi], bl[0], bl[1]);
                        mma_bf16(acc[w][mi][nj], al[mi], bh[0], bh[1]);
                    }
                }
            }
        }
    }

    // Epilogue: split-bf16 hi/lo into head-split q/k/v
#pragma unroll
    for (int w = 0; w < 3; w++) {
        __nv_bfloat16* Oh = (w == 0) ? g_qh : (w == 1) ? g_kh : g_vh;
        __nv_bfloat16* Ol = (w == 0) ? g_ql : (w == 1) ? g_kl : g_vl;
#pragma unroll
        for (int mi = 0; mi < 2; mi++) {
            const int r0 = m0 + wm * 32 + mi * 16 + (lane >> 2);
#pragma unroll
            for (int nj = 0; nj < 4; nj++) {
                const int dd = wn * 32 + nj * 8 + (lane & 3) * 2;
#pragma unroll
                for (int half = 0; half < 2; half++) {
                    int r = r0 + half * 8;
                    int b_ = r >> 12, s = r & 4095;
                    float a0 = acc[w][mi][nj][half * 2 + 0];
                    float a1 = acc[w][mi][nj][half * 2 + 1];
                    uint32_t lo, hi = pack_hilo(a0, a1, lo);
                    size_t idx = (((size_t)(b_ * HH + h)) * SS + s) * HDIM + dd;
                    *(uint32_t*)(Oh + idx) = hi;
                    *(uint32_t*)(Ol + idx) = lo;
                }
            }
        }
    }
}

// ---------------------------------------------------------------------------
// Output GEMM (mode-3 path of the proven R9 kernel): ctx @ Wu + bias -> out.
// 3-stage cp.async pipeline, CTA 128x128, K-chunk 32.
// ---------------------------------------------------------------------------
#define GK 32
#define SA2 40
#define SB2 136
#define SA_HI_B 0
#define SA_LO_B 10240
#define SB_HI_B 20480
#define SB_LO_B 29184
#define STAGE_B 37888
#define NSTAGE 3
#define GEMM_SMEM_BYTES (NSTAGE*STAGE_B)

__global__ __launch_bounds__(256, 2) void out_gemm_kernel(
    const float* __restrict__ bias, float* __restrict__ out_ptr)
{
    extern __shared__ __align__(16) char gsm[];
    const uint32_t smem_base = smem_u32(gsm);

    const int t    = threadIdx.x;
    const int lane = t & 31;
    const int wid  = t >> 5;
    const int wm   = wid & 3;
    const int wn   = wid >> 2;

    const int n0 = blockIdx.x * 128;
    const int m0 = blockIdx.y * 128;

    const __nv_bfloat16* Ahi = g_c_hi;
    const __nv_bfloat16* Alo = g_c_lo;
    const __nv_bfloat16* Bhi = g_w_hi + (size_t)3 * DD * DD;
    const __nv_bfloat16* Blo = g_w_lo + (size_t)3 * DD * DD;

    float acc[2][8][4];
#pragma unroll
    for (int mi = 0; mi < 2; mi++)
#pragma unroll
        for (int nj = 0; nj < 8; nj++)
#pragma unroll
            for (int e = 0; e < 4; e++) acc[mi][nj][e] = 0.f;

    const int lrow = lane & 15;
    const int lcol = (lane >> 4) * 8;

    const int arow0 = t >> 2,          aseg0 = (t & 3) * 8;
    const int arow1 = (t + 256) >> 2,  aseg1 = ((t + 256) & 3) * 8;
    const int brow0 = t >> 4,          bseg0 = (t & 15) * 8;
    const int brow1 = (t + 256) >> 4,  bseg1 = ((t + 256) & 15) * 8;

#define OGEMM_PREFETCH(KC, SBUF) do {                                       \
    const int k0_ = (KC) * GK;                                              \
    const uint32_t sb_ = smem_base + (uint32_t)(SBUF) * STAGE_B;            \
    {   size_t go = (size_t)(m0 + arow0) * DD + k0_ + aseg0;                \
        uint32_t so = sb_ + (uint32_t)(arow0 * SA2 + aseg0) * 2;            \
        cp_async16(so + SA_HI_B, Ahi + go);                                 \
        cp_async16(so + SA_LO_B, Alo + go); }                               \
    {   size_t go = (size_t)(m0 + arow1) * DD + k0_ + aseg1;                \
        uint32_t so = sb_ + (uint32_t)(arow1 * SA2 + aseg1) * 2;            \
        cp_async16(so + SA_HI_B, Ahi + go);                                 \
        cp_async16(so + SA_LO_B, Alo + go); }                               \
    {   size_t go = (size_t)(k0_ + brow0) * DD + n0 + bseg0;                \
        uint32_t so = sb_ + (uint32_t)(brow0 * SB2 + bseg0) * 2;            \
        cp_async16(so + SB_HI_B, Bhi + go);                                 \
        cp_async16(so + SB_LO_B, Blo + go); }                               \
    {   size_t go = (size_t)(k0_ + brow1) * DD + n0 + bseg1;                \
        uint32_t so = sb_ + (uint32_t)(brow1 * SB2 + bseg1) * 2;            \
        cp_async16(so + SB_HI_B, Bhi + go);                                 \
        cp_async16(so + SB_LO_B, Blo + go); }                               \
    CP_COMMIT; } while (0)

    OGEMM_PREFETCH(0, 0);
    OGEMM_PREFETCH(1, 1);

    int cs = 0;
    int ps = 2;
    for (int kc = 0; kc < 32; kc++) {
        if (kc <= 29) { CP_WAIT1; } else { CP_WAIT0; }
        __syncthreads();
        if (kc + 2 < 32) {
            OGEMM_PREFETCH(kc + 2, ps);
            ps = (ps + 1 == NSTAGE) ? 0 : ps + 1;
        }

        const uint32_t sb = smem_base + (uint32_t)cs * STAGE_B;
        cs = (cs + 1 == NSTAGE) ? 0 : cs + 1;
#pragma unroll
        for (int kk = 0; kk < 2; kk++) {
            uint32_t ah[2][4], al[2][4];
#pragma unroll
            for (int mi = 0; mi < 2; mi++) {
                uint32_t off = (uint32_t)((wm * 32 + mi * 16 + lrow) * SA2 + kk * 16 + lcol) * 2;
                ldsm_x4(ah[mi], sb + SA_HI_B + off);
                ldsm_x4(al[mi], sb + SA_LO_B + off);
            }
            uint32_t bh[8][2], bl[8][2];
#pragma unroll
            for (int nj = 0; nj < 8; nj++) {
                uint32_t off = (uint32_t)((kk * 16 + lrow) * SB2 + wn * 64 + nj * 8) * 2;
                ldsm_x2_trans(bh[nj], sb + SB_HI_B + off);
                ldsm_x2_trans(bl[nj], sb + SB_LO_B + off);
            }
#pragma unroll
            for (int mi = 0; mi < 2; mi++)
#pragma unroll
                for (int nj = 0; nj < 8; nj++) {
                    mma_bf16(acc[mi][nj], ah[mi], bh[nj][0], bh[nj][1]);
                    mma_bf16(acc[mi][nj], ah[mi], bl[nj][0], bl[nj][1]);
                    mma_bf16(acc[mi][nj], al[mi], bh[nj][0], bh[nj][1]);
                }
        }
    }

    // Epilogue
#pragma unroll
    for (int mi = 0; mi < 2; mi++) {
        const int r0 = m0 + wm * 32 + mi * 16 + (lane >> 2);
#pragma unroll
        for (int nj = 0; nj < 8; nj++) {
            const int col = wn * 64 + nj * 8 + (lane & 3) * 2;
            float bv0 = bias[n0 + col], bv1 = bias[n0 + col + 1];
            float2 st0; st0.x = acc[mi][nj][0] + bv0; st0.y = acc[mi][nj][1] + bv1;
            float2 st1; st1.x = acc[mi][nj][2] + bv0; st1.y = acc[mi][nj][3] + bv1;
            *(float2*)(out_ptr + (size_t)r0 * DD + n0 + col) = st0;
            *(float2*)(out_ptr + (size_t)(r0 + 8) * DD + n0 + col) = st1;
        }
    }
}

// ---------------------------------------------------------------------------
// BigBird sparse attention on HMMA, split-KV heavy blocks, cp.async pipelined
// (unchanged from R9 / proven state).
// ---------------------------------------------------------------------------
#define ATT_STRB 144                  // 72 b16 row stride, in bytes
#define KSTAGE(s) ((s) * 18432)       // per stage: KH +0, KL +9216
#define T_VH 36864
#define T_VL 46080
#define T_PEN2 55296                  // raw band_mask floats, 64 x 68 (stride 272B)
#define T_PEN1 72704                  // raw to_mask slice, 64 floats
#define ATTN_SMEM_BYTES 72976

__global__ __launch_bounds__(128, 3) void attn_kernel(
    const float* __restrict__ band_mask,
    const float* __restrict__ from_mask,
    const float* __restrict__ to_mask)
{
    extern __shared__ __align__(16) char smraw[];
    const uint32_t smem_base = smem_u32(smraw);
    const float* pen2f = (const float*)(smraw + T_PEN2);
    const float* pen1f = (const float*)(smraw + T_PEN1);

    const int bx = blockIdx.x;
    const int h  = blockIdx.y;
    const int b  = blockIdx.z;
    const int t  = threadIdx.x;
    const int lane = t & 31;
    const int wid  = t >> 5;

    const bool heavy = (bx >= 62);
    int qb, ch = 0;
    if (heavy) { int hx = bx - 62; qb = hx >> 3; ch = hx & 7; }
    else qb = bx + 2;

    const float rs  = 0.125f;
    const float pen = -10000.f;
    const size_t bh64 = ((size_t)(b * HH + h)) * SS * HDIM;

    // ---- Load Q tile (hi/lo) into K-stage-0 area, extract frags ----
    {
        const __nv_bfloat16* qhp = g_qh + bh64 + (size_t)qb * BLKSZ * HDIM;
        const __nv_bfloat16* qlp = g_ql + bh64 + (size_t)qb * BLKSZ * HDIM;
        for (int i = t; i < 512; i += 128) {
            int row = i >> 3, seg = (i & 7) * 8;
            *(uint4*)(smraw + row * ATT_STRB + seg * 2)        = *(const uint4*)(qhp + row * HDIM + seg);
            *(uint4*)(smraw + 9216 + row * ATT_STRB + seg * 2) = *(const uint4*)(qlp + row * HDIM + seg);
        }
    }
    __syncthreads();

    uint32_t qfh[4][4], qfl[4][4];
    {
        const int lrow = lane & 15;
        const int lcol = (lane >> 4) * 8;
#pragma unroll
        for (int kk = 0; kk < 4; kk++) {
            uint32_t off = (uint32_t)((wid * 16 + lrow) * ATT_STRB + (kk * 16 + lcol) * 2);
            ldsm_x4(qfh[kk], smem_base + off);
            ldsm_x4(qfl[kk], smem_base + 9216 + off);
        }
    }
    __syncthreads();   // everyone done reading Q before K(0) cp.async overwrites

    // ---- schedule ----
    int nt;
    int kbs[5];
    bool is_band = false;
    if (heavy) {
        nt = 8;
    } else if (qb == NGB) {
        nt = 5; kbs[0]=0; kbs[1]=1; kbs[2]=2; kbs[3]=3; kbs[4]=4;
    } else if (qb == NB - 1) {
        nt = 5; kbs[0]=0; kbs[1]=1; kbs[2]=61; kbs[3]=62; kbs[4]=63;
    } else {
        nt = 5; kbs[0]=0; kbs[1]=1; kbs[2]=qb-1; kbs[3]=qb; kbs[4]=qb+1; is_band = true;
    }

#define KB_OF(IT) (heavy ? (ch * 8 + (IT)) : kbs[(IT)])

    // ---- cp.async issue helpers ----
#define ISSUE_K(KB, STG) do {                                               \
    const __nv_bfloat16* khp_ = g_kh + bh64 + (size_t)(KB) * BLKSZ * HDIM;  \
    const __nv_bfloat16* klp_ = g_kl + bh64 + (size_t)(KB) * BLKSZ * HDIM;  \
    for (int i = t; i < 512; i += 128) {                                    \
        int row = i >> 3, seg = (i & 7) * 8;                                \
        uint32_t so = smem_base + KSTAGE(STG) + row * ATT_STRB + seg * 2;   \
        cp_async16(so,        khp_ + row * HDIM + seg);                     \
        cp_async16(so + 9216, klp_ + row * HDIM + seg);                     \
    }                                                                       \
    CP_COMMIT; } while (0)

#define ISSUE_VP(IT, KB, BANDT) do {                                        \
    const __nv_bfloat16* vhp_ = g_vh + bh64 + (size_t)(KB) * BLKSZ * HDIM;  \
    const __nv_bfloat16* vlp_ = g_vl + bh64 + (size_t)(KB) * BLKSZ * HDIM;  \
    for (int i = t; i < 512; i += 128) {                                    \
        int row = i >> 3, seg = (i & 7) * 8;                                \
        uint32_t so = smem_base + T_VH + row * ATT_STRB + seg * 2;          \
        cp_async16(so,        vhp_ + row * HDIM + seg);                     \
        cp_async16(so + 9216, vlp_ + row * HDIM + seg);                     \
    }                                                                       \
    if (BANDT) {                                                            \
        const float* bmb_ = band_mask                                       \
            + ((size_t)(b * 60 + (qb - 3)) * 64) * 192 + (size_t)((IT) - 2) * 64; \
        for (int i = t; i < 1024; i += 128) {                               \
            int row = i >> 4, c = i & 15;                                   \
            cp_async16(smem_base + T_PEN2 + row * 272 + c * 16,             \
                       bmb_ + row * 192 + c * 4);                           \
        }                                                                   \
    } else if (t < 16) {                                                    \
        cp_async16(smem_base + T_PEN1 + t * 16,                             \
                   to_mask + (size_t)b * SS + (KB) * BLKSZ + t * 4);        \
    }                                                                       \
    CP_COMMIT; } while (0)

    // ---- flash state ----
    float m0 = -1e30f, m1 = -1e30f, l0 = 0.f, l1 = 0.f;
    float o[8][4];
#pragma unroll
    for (int nj = 0; nj < 8; nj++)
#pragma unroll
        for (int e = 0; e < 4; e++) o[nj][e] = 0.f;

    // prologue: K(0) -> stage 0
    ISSUE_K(KB_OF(0), 0);

    for (int it = 0; it < nt; it++) {
        const int kb = KB_OF(it);
        const bool band_tile = (is_band && it >= 2);

        ISSUE_VP(it, kb, band_tile);
        if (it + 1 < nt) {
            ISSUE_K(KB_OF(it + 1), (it + 1) & 1);
            CP_WAIT2;            // K(it) landed (VP(it), K(it+1) may be pending)
        } else {
            CP_WAIT1;            // K(it) landed (VP(it) may be pending)
        }
        __syncthreads();

        // ---- Scores: S = Q K^T (split precision), K from stage it&1 ----
        const uint32_t kst = smem_base + KSTAGE(it & 1);
        float acc[8][4];
#pragma unroll
        for (int nj = 0; nj < 8; nj++)
#pragma unroll
            for (int e = 0; e < 4; e++) acc[nj][e] = 0.f;

#pragma unroll
        for (int nj = 0; nj < 8; nj++) {
            uint32_t kh8[8], kl8[8];
            uint32_t rbase = (uint32_t)((nj * 8 + (lane & 7)) * ATT_STRB + (lane >> 3) * 16);
            ldsm_x4(kh8,     kst + rbase);
            ldsm_x4(kh8 + 4, kst + rbase + 64);
            ldsm_x4(kl8,     kst + 9216 + rbase);
            ldsm_x4(kl8 + 4, kst + 9216 + rbase + 64);
#pragma unroll
            for (int kk = 0; kk < 4; kk++) {
                mma_bf16(acc[nj], qfh[kk], kh8[2*kk], kh8[2*kk+1]);
                mma_bf16(acc[nj], qfh[kk], kl8[2*kk], kl8[2*kk+1]);
                mma_bf16(acc[nj], qfl[kk], kh8[2*kk], kh8[2*kk+1]);
            }
        }

        // ---- V + mask data ready? ----
        if (it + 1 < nt) { CP_WAIT1; } else { CP_WAIT0; }
        __syncthreads();

        // ---- Scale + mask ((1-m)*pen computed inline from raw masks) ----
        const int qr0 = wid * 16 + (lane >> 2);
#pragma unroll
        for (int nj = 0; nj < 8; nj++) {
#pragma unroll
            for (int e = 0; e < 4; e++) {
                int col = nj * 8 + (lane & 3) * 2 + (e & 1);
                float mv = band_tile
                    ? pen2f[(qr0 + (e >> 1) * 8) * 68 + col]
                    : pen1f[col];
                acc[nj][e] = acc[nj][e] * rs + (1.f - mv) * pen;
            }
        }

        // ---- Streaming softmax ----
        float tm0 = -1e30f, tm1 = -1e30f;
#pragma unroll
        for (int nj = 0; nj < 8; nj++) {
            tm0 = fmaxf(tm0, fmaxf(acc[nj][0], acc[nj][1]));
            tm1 = fmaxf(tm1, fmaxf(acc[nj][2], acc[nj][3]));
        }
        tm0 = fmaxf(tm0, __shfl_xor_sync(0xffffffffu, tm0, 1));
        tm0 = fmaxf(tm0, __shfl_xor_sync(0xffffffffu, tm0, 2));
        tm1 = fmaxf(tm1, __shfl_xor_sync(0xffffffffu, tm1, 1));
        tm1 = fmaxf(tm1, __shfl_xor_sync(0xffffffffu, tm1, 2));

        float nm0 = fmaxf(m0, tm0), nm1 = fmaxf(m1, tm1);
        float c0 = __expf(m0 - nm0), c1 = __expf(m1 - nm1);
        float ts0 = 0.f, ts1 = 0.f;
#pragma unroll
        for (int nj = 0; nj < 8; nj++) {
            acc[nj][0] = __expf(acc[nj][0] - nm0);
            acc[nj][1] = __expf(acc[nj][1] - nm0);
            acc[nj][2] = __expf(acc[nj][2] - nm1);
            acc[nj][3] = __expf(acc[nj][3] - nm1);
            ts0 += acc[nj][0] + acc[nj][1];
            ts1 += acc[nj][2] + acc[nj][3];
        }
        ts0 += __shfl_xor_sync(0xffffffffu, ts0, 1);
        ts0 += __shfl_xor_sync(0xffffffffu, ts0, 2);
        ts1 += __shfl_xor_sync(0xffffffffu, ts1, 1);
        ts1 += __shfl_xor_sync(0xffffffffu, ts1, 2);
        l0 = l0 * c0 + ts0;  l1 = l1 * c1 + ts1;
        m0 = nm0;  m1 = nm1;
#pragma unroll
        for (int nj = 0; nj < 8; nj++) {
            o[nj][0] *= c0; o[nj][1] *= c0;
            o[nj][2] *= c1; o[nj][3] *= c1;
        }

        // ---- Pack P -> A-frags (bf16 hi/lo) ----
        uint32_t phi[4][4], plo[4][4];
#pragma unroll
        for (int kk2 = 0; kk2 < 4; kk2++) {
            phi[kk2][0] = pack_hilo(acc[2*kk2][0],   acc[2*kk2][1],   plo[kk2][0]);
            phi[kk2][1] = pack_hilo(acc[2*kk2][2],   acc[2*kk2][3],   plo[kk2][1]);
            phi[kk2][2] = pack_hilo(acc[2*kk2+1][0], acc[2*kk2+1][1], plo[kk2][2]);
            phi[kk2][3] = pack_hilo(acc[2*kk2+1][2], acc[2*kk2+1][3], plo[kk2][3]);
        }

        // ---- PV: O += P V (split precision, x2_trans V loads) ----
#pragma unroll
        for (int njd = 0; njd < 8; njd++) {
#pragma unroll
            for (int kk2 = 0; kk2 < 4; kk2++) {
                uint32_t vh[2], vl[2];
                uint32_t off = (uint32_t)((kk2 * 16 + (lane & 15)) * ATT_STRB + njd * 16);
                ldsm_x2_trans(vh, smem_base + T_VH + off);
                ldsm_x2_trans(vl, smem_base + T_VL + off);
                mma_bf16(o[njd], phi[kk2], vh[0], vh[1]);
                mma_bf16(o[njd], phi[kk2], vl[0], vl[1]);
                mma_bf16(o[njd], plo[kk2], vh[0], vh[1]);
            }
        }
        __syncthreads();   // protect V buffer + masks before next iter's issue
    }

    const int r0 = wid * 16 + (lane >> 2);
    if (!heavy) {
        const int s0 = qb * BLKSZ + r0;
        const int s1 = s0 + 8;
        float inv0 = from_mask[(size_t)b * SS + s0] / l0;
        float inv1 = from_mask[(size_t)b * SS + s1] / l1;
#pragma unroll
        for (int njd = 0; njd < 8; njd++) {
            const int col = njd * 8 + (lane & 3) * 2;
            {
                size_t idx = ((size_t)b * SS + s0) * DD + h * HDIM + col;
                uint32_t lo, hi = pack_hilo(o[njd][0] * inv0, o[njd][1] * inv0, lo);
                *(uint32_t*)(g_c_hi + idx) = hi;
                *(uint32_t*)(g_c_lo + idx) = lo;
            }
            {
                size_t idx = ((size_t)b * SS + s1) * DD + h * HDIM + col;
                uint32_t lo, hi = pack_hilo(o[njd][2] * inv1, o[njd][3] * inv1, lo);
                *(uint32_t*)(g_c_hi + idx) = hi;
                *(uint32_t*)(g_c_lo + idx) = lo;
            }
        }
    } else {
        const int cid = ((b * HH + h) * 2 + qb) * 8 + ch;
        float* pob = g_po + (size_t)cid * 4096;
#pragma unroll
        for (int njd = 0; njd < 8; njd++) {
            const int col = njd * 8 + (lane & 3) * 2;
            float2 s0v; s0v.x = o[njd][0]; s0v.y = o[njd][1];
            float2 s1v; s1v.x = o[njd][2]; s1v.y = o[njd][3];
            *(float2*)(pob + r0 * 64 + col) = s0v;
            *(float2*)(pob + (r0 + 8) * 64 + col) = s1v;
        }
        if ((lane & 3) == 0) {
            g_pm[cid * 64 + r0]     = m0;
            g_pm[cid * 64 + r0 + 8] = m1;
            g_pl[cid * 64 + r0]     = l0;
            g_pl[cid * 64 + r0 + 8] = l1;
        }
    }
}

// ---------------------------------------------------------------------------
// Combine split-KV partials for heavy q-blocks.
// ---------------------------------------------------------------------------
__global__ __launch_bounds__(128) void attn_combine(const float* __restrict__ from_mask)
{
    const int x  = blockIdx.x;
    const int qb = x & 1;
    const int h  = (x >> 1) & 15;
    const int b  = x >> 5;
    const int t  = threadIdx.x;
    const int r  = t >> 1;
    const int c0 = (t & 1) * 32;
    const int base8 = x * 8;

    float m[8], l[8], M = -1e30f;
#pragma unroll
    for (int i = 0; i < 8; i++) {
        m[i] = g_pm[(base8 + i) * 64 + r];
        l[i] = g_pl[(base8 + i) * 64 + r];
        M = fmaxf(M, m[i]);
    }
    float L = 0.f, sc[8];
#pragma unroll
    for (int i = 0; i < 8; i++) { sc[i] = __expf(m[i] - M); L += l[i] * sc[i]; }

    float acc[32];
#pragma unroll
    for (int c = 0; c < 32; c++) acc[c] = 0.f;
#pragma unroll
    for (int i = 0; i < 8; i++) {
        const float* p = g_po + (size_t)(base8 + i) * 4096 + r * 64 + c0;
        float s = sc[i];
#pragma unroll
        for (int c4 = 0; c4 < 8; c4++) {
            float4 v = *(const float4*)(p + c4 * 4);
            acc[c4*4+0] += s * v.x; acc[c4*4+1] += s * v.y;
            acc[c4*4+2] += s * v.z; acc[c4*4+3] += s * v.w;
        }
    }

    const int s_ = qb * BLKSZ + r;
    float inv = from_mask[(size_t)b * SS + s_] / L;
    size_t idx = ((size_t)b * SS + s_) * DD + h * HDIM + c0;
#pragma unroll
    for (int c = 0; c < 32; c += 2) {
        uint32_t lo, hi = pack_hilo(acc[c] * inv, acc[c+1] * inv, lo);
        *(uint32_t*)(g_c_hi + idx + c) = hi;
        *(uint32_t*)(g_c_lo + idx + c) = lo;
    }
}

// ---------------------------------------------------------------------------
extern "C" void kernel_launch(void* const* d_in, const int* in_sizes, int n_in,
                              void* d_out, int out_size)
{
    const float* tokens    = (const float*)d_in[0];
    const float* band_mask = (const float*)d_in[1];
    const float* from_mask = (const float*)d_in[2];
    const float* to_mask   = (const float*)d_in[3];
    const float* Wq        = (const float*)d_in[4];
    const float* Wk        = (const float*)d_in[5];
    const float* Wv        = (const float*)d_in[6];
    const float* Wu        = (const float*)d_in[7];
    const float* bu        = (const float*)d_in[8];
    float* out = (float*)d_out;

    cudaFuncSetAttribute(attn_kernel,
                         cudaFuncAttributeMaxDynamicSharedMemorySize, ATTN_SMEM_BYTES);
    cudaFuncSetAttribute(out_gemm_kernel,
                         cudaFuncAttributeMaxDynamicSharedMemorySize, GEMM_SMEM_BYTES);
    cudaFuncSetAttribute(qkv_fused_kernel,
                         cudaFuncAttributeMaxDynamicSharedMemorySize, FQKV_SMEM_BYTES);

    // 0) Precision-split inputs and weights
    split_x_kernel<<<(MROWS * DD / 4) / 256, 256>>>(tokens);
    wsplit_kernel<<<dim3(1024, 4), 256>>>(Wq, Wk, Wv, Wu);

    // 1) Fused QKV projections (A-fragment reuse across q/k/v)
    qkv_fused_kernel<<<dim3(16, 64), 256, FQKV_SMEM_BYTES>>>();

    // 2) Sparse attention (light + split-KV heavy in one grid, cp.async pipelined)
    attn_kernel<<<dim3(78, HH, BB), 128, ATTN_SMEM_BYTES>>>(band_mask, from_mask, to_mask);

    // 2b) Combine heavy partials
    attn_combine<<<64, 128>>>(from_mask);

    // 3) Output projection + bias (3-stage pipelined HMMA)
    out_gemm_kernel<<<dim3(8, 64), 256, GEMM_SMEM_BYTES>>>(bu, out);
}